// round 15
// baseline (speedup 1.0000x reference)
#include <cuda_runtime.h>
#include <cuda_fp16.h>
#include <mma.h>
#include <cstdint>

using namespace nvcuda;

#define NN 50000
#define EE 600000
#define DD 128
#define HH 256
#define LL 6
#define SCB 256
#define NSCB ((NN + SCB - 1) / SCB)   // 196

__device__ __align__(128) float d_h [NN * DD];
__device__ __align__(128) float d_g [NN * DD];
__device__ __align__(128) __half2 d_pqh[NN * DD];
__device__ __align__(16) __half d_noh[NN * DD];   // agg+g, fp16
__device__ __align__(16) __half d_zh [NN * HH];   // MLP hidden, fp16
__device__ int d_deg[NN];
__device__ int d_rowptr[NN + 1];
__device__ int d_cursor[NN];
__device__ int d_colsrc[EE];
__device__ int d_blksum[NSCB];
__device__ int d_is64;

#define WT_TOTAL 425984
__device__ __align__(16) __half d_wtb[WT_TOTAL];  // weights, single fp16

__device__ __forceinline__ int edge_at(const void* ei, int is64, size_t pos) {
    int v;
    if (is64) v = (int)((const long long*)ei)[pos];
    else      v = ((const int*)ei)[pos];
    if (v < 0) v = 0;
    if (v >= NN) v = NN - 1;
    return v;
}

__global__ void k_probe(const void* ei) {
    __shared__ int bad;
    if (threadIdx.x == 0) bad = 0;
    __syncthreads();
    const long long* p = (const long long*)ei;
    for (int i = threadIdx.x; i < 1024; i += blockDim.x) {
        long long v = p[i];
        if (v < 0 || v >= NN) bad = 1;
    }
    __syncthreads();
    if (threadIdx.x == 0) d_is64 = bad ? 0 : 1;
}

__global__ void k_zero_deg() {
    int i = blockIdx.x * blockDim.x + threadIdx.x;
    if (i < NN) d_deg[i] = 0;
}
__global__ void k_count(const void* __restrict__ ei) {
    int e = blockIdx.x * blockDim.x + threadIdx.x;
    if (e < EE) atomicAdd(&d_deg[edge_at(ei, d_is64, (size_t)EE + e)], 1);
}
__global__ void k_scan1() {
    __shared__ int sm[SCB];
    int t = threadIdx.x;
    int i = blockIdx.x * SCB + t;
    sm[t] = (i < NN) ? d_deg[i] : 0;
    __syncthreads();
#pragma unroll
    for (int off = SCB / 2; off; off >>= 1) {
        if (t < off) sm[t] += sm[t + off];
        __syncthreads();
    }
    if (t == 0) d_blksum[blockIdx.x] = sm[0];
}
__global__ void k_scan2() {
    __shared__ int sm[SCB];
    int t = threadIdx.x;
    int v = (t < NSCB) ? d_blksum[t] : 0;
    sm[t] = v;
    __syncthreads();
#pragma unroll
    for (int off = 1; off < SCB; off <<= 1) {
        int u = (t >= off) ? sm[t - off] : 0;
        __syncthreads();
        sm[t] += u;
        __syncthreads();
    }
    if (t < NSCB) d_blksum[t] = sm[t] - v;
    if (t == SCB - 1) d_rowptr[NN] = sm[SCB - 1];
}
__global__ void k_scan3() {
    __shared__ int sm[SCB];
    int t = threadIdx.x;
    int i = blockIdx.x * SCB + t;
    int v = (i < NN) ? d_deg[i] : 0;
    sm[t] = v;
    __syncthreads();
#pragma unroll
    for (int off = 1; off < SCB; off <<= 1) {
        int u = (t >= off) ? sm[t - off] : 0;
        __syncthreads();
        sm[t] += u;
        __syncthreads();
    }
    int excl = sm[t] - v + d_blksum[blockIdx.x];
    if (i < NN) { d_rowptr[i] = excl; d_cursor[i] = excl; }
}
__global__ void k_fill(const void* __restrict__ ei) {
    int e = blockIdx.x * blockDim.x + threadIdx.x;
    if (e < EE) {
        int dst = edge_at(ei, d_is64, (size_t)EE + e);
        int src = edge_at(ei, d_is64, (size_t)e);
        int pos = atomicAdd(&d_cursor[dst], 1);
        if (pos >= 0 && pos < EE) d_colsrc[pos] = src;
    }
}

__global__ void k_tsplit_all(const float* __restrict__ encW, const float* __restrict__ W1,
                             const float* __restrict__ W2, const float* __restrict__ lW1) {
    int idx = blockIdx.x * blockDim.x + threadIdx.x;
    if (idx >= WT_TOTAL) return;
    float v;
    if (idx < 16384) {
        int n = idx >> 7, k = idx & 127;
        v = encW[k * 128 + n];
    } else if (idx < 409600) {
        int r = (idx - 16384) >> 15;
        int wi = (idx - 16384) & 32767;
        if (r < 6) {
            int n = wi >> 7, k = wi & 127;
            v = W1[(size_t)r * 32768 + k * 256 + n];
        } else {
            int n = wi >> 8, k = wi & 255;
            v = W2[(size_t)(r - 6) * 32768 + k * 128 + n];
        }
    } else {
        int wi = idx - 409600;
        int n = wi >> 7, k = wi & 127;
        v = lW1[k * 128 + n];
    }
    d_wtb[idx] = __float2half_rn(v);
}

__device__ __forceinline__ float warp_sum(float v) {
#pragma unroll
    for (int off = 16; off; off >>= 1) v += __shfl_xor_sync(0xffffffffu, v, off);
    return v;
}

__device__ __forceinline__ uint2 to_h4(float4 v) {
    __half2 h01 = __floats2half2_rn(v.x, v.y);
    __half2 h23 = __floats2half2_rn(v.z, v.w);
    return make_uint2(*reinterpret_cast<uint32_t*>(&h01), *reinterpret_cast<uint32_t*>(&h23));
}

__device__ __forceinline__ void pq_acc(uint4 u, float4& den, float4& num) {
    float2 f0 = __half22float2(*reinterpret_cast<__half2*>(&u.x));
    float2 f1 = __half22float2(*reinterpret_cast<__half2*>(&u.y));
    float2 f2 = __half22float2(*reinterpret_cast<__half2*>(&u.z));
    float2 f3 = __half22float2(*reinterpret_cast<__half2*>(&u.w));
    den.x += f0.x; num.x += f0.y;
    den.y += f1.x; num.y += f1.y;
    den.z += f2.x; num.z += f2.y;
    den.w += f3.x; num.w += f3.y;
}

// ---------------- standalone CSR gather, fp16 output ----------------
__global__ void k_agg() {
    int n = (blockIdx.x * blockDim.x + threadIdx.x) >> 5;
    if (n >= NN) return;
    int lane = threadIdx.x & 31;
    int beg = d_rowptr[n], end = d_rowptr[n + 1];
    float4 den = make_float4(0.f, 0.f, 0.f, 0.f);
    float4 num = make_float4(0.f, 0.f, 0.f, 0.f);
    int e = beg;
    for (; e + 3 < end; e += 4) {
        int s0 = d_colsrc[e + 0], s1 = d_colsrc[e + 1];
        int s2 = d_colsrc[e + 2], s3 = d_colsrc[e + 3];
        uint4 u0 = *reinterpret_cast<const uint4*>(&d_pqh[(size_t)s0 * DD + lane * 4]);
        uint4 u1 = *reinterpret_cast<const uint4*>(&d_pqh[(size_t)s1 * DD + lane * 4]);
        uint4 u2 = *reinterpret_cast<const uint4*>(&d_pqh[(size_t)s2 * DD + lane * 4]);
        uint4 u3 = *reinterpret_cast<const uint4*>(&d_pqh[(size_t)s3 * DD + lane * 4]);
        pq_acc(u0, den, num);
        pq_acc(u1, den, num);
        pq_acc(u2, den, num);
        pq_acc(u3, den, num);
    }
    for (; e < end; e++) {
        int s = d_colsrc[e];
        uint4 u = *reinterpret_cast<const uint4*>(&d_pqh[(size_t)s * DD + lane * 4]);
        pq_acc(u, den, num);
    }
    float4 gv = *reinterpret_cast<const float4*>(&d_g[(size_t)n * DD + lane * 4]);
    float4 o;
    o.x = gv.x + num.x / (den.x + 1e-16f);
    o.y = gv.y + num.y / (den.y + 1e-16f);
    o.z = gv.z + num.z / (den.z + 1e-16f);
    o.w = gv.w + num.w / (den.w + 1e-16f);
    *reinterpret_cast<uint2*>(&d_noh[(size_t)n * DD + lane * 4]) = to_h4(o);
}

#define ALD 136
#define CLD 132
#define CLD2 260

// ---------------- gemm_std: 64-row tiles, 2 CTAs/SM, 32x32 warp tiles, single-term fp16 ----------------
template <int TK, bool PRESPLIT, bool RESID, bool DO_MSG, bool RELU, bool HEAD>
__global__ void __launch_bounds__(256, 2) gemm_std(const float* Ap, int Aid, int wtoff,
                                                   const float* __restrict__ bias,
                                                   const float* __restrict__ gamma,
                                                   const float* __restrict__ beta,
                                                   const float* __restrict__ tptr, int li,
                                                   const float* __restrict__ w2h,
                                                   const float* __restrict__ b2h,
                                                   float* __restrict__ outp) {
    extern __shared__ char smem[];
    __half* SA = (__half*)smem;             // 64 x ALD
    __half* SB = SA + 64 * ALD;             // 128 x ALD
    float* SC = (float*)smem;

    const int tid = threadIdx.x;
    const int w = tid >> 5, lane = tid & 31;
    const int rg = w >> 2;
    const int cg = w & 3;
    const int m0 = blockIdx.x * 64;

    const float* __restrict__ A = (Aid == 1) ? d_h : Ap;

    wmma::fragment<wmma::accumulator, 16, 16, 16, float> acc[2][2];
#pragma unroll
    for (int i = 0; i < 2; i++)
#pragma unroll
        for (int j = 0; j < 2; j++) wmma::fill_fragment(acc[i][j], 0.0f);

    constexpr int CHUNKS = TK / 128;
    for (int kc = 0; kc < CHUNKS; kc++) {
        __syncthreads();
        if (PRESPLIT) {
            for (int idx = tid; idx < 64 * 16; idx += 256) {
                int row = idx >> 4, seg = idx & 15;
                uint4 v = make_uint4(0u, 0u, 0u, 0u);
                if (m0 + row < NN)
                    v = *reinterpret_cast<const uint4*>(&d_zh[(size_t)(m0 + row) * TK + kc * 128 + seg * 8]);
                *reinterpret_cast<uint4*>(&SA[row * ALD + seg * 8]) = v;
            }
        } else {
            for (int idx = tid; idx < 64 * 32; idx += 256) {
                int row = idx >> 5, seg = idx & 31;
                float4 v = make_float4(0.f, 0.f, 0.f, 0.f);
                if (m0 + row < NN)
                    v = *reinterpret_cast<const float4*>(&A[(size_t)(m0 + row) * TK + kc * 128 + seg * 4]);
                *reinterpret_cast<uint2*>(&SA[row * ALD + seg * 4]) = to_h4(v);
            }
        }
        for (int idx = tid; idx < 128 * 16; idx += 256) {
            int row = idx >> 4, seg = idx & 15;
            size_t src = (size_t)wtoff + (size_t)row * TK + kc * 128 + seg * 8;
            *reinterpret_cast<uint4*>(&SB[row * ALD + seg * 8]) =
                *reinterpret_cast<const uint4*>(&d_wtb[src]);
        }
        __syncthreads();
#pragma unroll
        for (int ks = 0; ks < 8; ks++) {
            wmma::fragment<wmma::matrix_a, 16, 16, 16, __half, wmma::row_major> a[2];
#pragma unroll
            for (int i = 0; i < 2; i++)
                wmma::load_matrix_sync(a[i], &SA[(rg * 32 + i * 16) * ALD + ks * 16], ALD);
#pragma unroll
            for (int j = 0; j < 2; j++) {
                wmma::fragment<wmma::matrix_b, 16, 16, 16, __half, wmma::col_major> b;
                wmma::load_matrix_sync(b, &SB[(cg * 32 + j * 16) * ALD + ks * 16], ALD);
#pragma unroll
                for (int i = 0; i < 2; i++)
                    wmma::mma_sync(acc[i][j], a[i], b, acc[i][j]);
            }
        }
    }
    __syncthreads();
#pragma unroll
    for (int i = 0; i < 2; i++)
#pragma unroll
        for (int j = 0; j < 2; j++)
            wmma::store_matrix_sync(&SC[(rg * 32 + i * 16) * CLD + cg * 32 + j * 16],
                                    acc[i][j], CLD, wmma::mem_row_major);
    __syncthreads();

    const int col = lane * 4;
    float tval = 0.f;
    if (DO_MSG) tval = tptr[li];
    float4 bi = *reinterpret_cast<const float4*>(&bias[col]);
    float4 gm, bt;
    if (DO_MSG) {
        gm = *reinterpret_cast<const float4*>(&gamma[col]);
        bt = *reinterpret_cast<const float4*>(&beta[col]);
    }
    float hw00 = 0.f, hw01 = 0.f, hw10 = 0.f, hw11 = 0.f, hw20 = 0.f, hw21 = 0.f, hw30 = 0.f, hw31 = 0.f;
    if (HEAD) {
        hw00 = w2h[(col + 0) * 2 + 0]; hw01 = w2h[(col + 0) * 2 + 1];
        hw10 = w2h[(col + 1) * 2 + 0]; hw11 = w2h[(col + 1) * 2 + 1];
        hw20 = w2h[(col + 2) * 2 + 0]; hw21 = w2h[(col + 2) * 2 + 1];
        hw30 = w2h[(col + 3) * 2 + 0]; hw31 = w2h[(col + 3) * 2 + 1];
    }
#pragma unroll 1
    for (int rr = 0; rr < 8; rr++) {
        int row = w * 8 + rr;
        int r = m0 + row;
        if (r >= NN) continue;
        float4 v = *reinterpret_cast<const float4*>(&SC[row * CLD + col]);
        v.x += bi.x; v.y += bi.y; v.z += bi.z; v.w += bi.w;
        if (RESID) {
            float4 h4 = *reinterpret_cast<const float4*>(&d_h[(size_t)r * DD + col]);
            v.x += h4.x; v.y += h4.y; v.z += h4.z; v.w += h4.w;
        }
        if (RELU) {
            v.x = fmaxf(v.x, 0.f); v.y = fmaxf(v.y, 0.f);
            v.z = fmaxf(v.z, 0.f); v.w = fmaxf(v.w, 0.f);
        }
        if (HEAD) {
            float a0 = v.x * hw00 + v.y * hw10 + v.z * hw20 + v.w * hw30;
            float a1 = v.x * hw01 + v.y * hw11 + v.z * hw21 + v.w * hw31;
            a0 = warp_sum(a0);
            a1 = warp_sum(a1);
            if (lane == 0) {
                outp[r * 2 + 0] = a0 + b2h[0];
                outp[r * 2 + 1] = a1 + b2h[1];
            }
            continue;
        }
        *reinterpret_cast<float4*>(&d_h[(size_t)r * DD + col]) = v;
        if (DO_MSG) {
            float s = warp_sum(v.x + v.y + v.z + v.w);
            float mu = s * (1.0f / DD);
            float dx = v.x - mu, dy = v.y - mu, dz = v.z - mu, dw = v.w - mu;
            float ss = warp_sum(dx * dx + dy * dy + dz * dz + dw * dw);
            float inv = rsqrtf(ss * (1.0f / DD) + 1e-5f);
            float g0 = fmaxf(dx * inv * gm.x + bt.x, 0.0f);
            float g1 = fmaxf(dy * inv * gm.y + bt.y, 0.0f);
            float g2 = fmaxf(dz * inv * gm.z + bt.z, 0.0f);
            float g3 = fmaxf(dw * inv * gm.w + bt.w, 0.0f);
            *reinterpret_cast<float4*>(&d_g[(size_t)r * DD + col]) = make_float4(g0, g1, g2, g3);
            float m0f = g0 + 1e-7f, m1f = g1 + 1e-7f, m2f = g2 + 1e-7f, m3f = g3 + 1e-7f;
            float p0 = __expf(tval * m0f), p1 = __expf(tval * m1f);
            float p2 = __expf(tval * m2f), p3 = __expf(tval * m3f);
            __half2 pq0 = __floats2half2_rn(p0, m0f * p0);
            __half2 pq1 = __floats2half2_rn(p1, m1f * p1);
            __half2 pq2 = __floats2half2_rn(p2, m2f * p2);
            __half2 pq3 = __floats2half2_rn(p3, m3f * p3);
            uint4 u = make_uint4(*reinterpret_cast<uint32_t*>(&pq0), *reinterpret_cast<uint32_t*>(&pq1),
                                 *reinterpret_cast<uint32_t*>(&pq2), *reinterpret_cast<uint32_t*>(&pq3));
            *reinterpret_cast<uint4*>(&d_pqh[(size_t)r * DD + col]) = u;
        }
    }
}

// ---------------- gemm_mlp1: 64x256 tile, 256 threads, 2 CTAs/SM, 32x64 warp tiles ----------------
// Single pass (single-term B). LN(256)+relu epilogue -> d_zh.
__global__ void __launch_bounds__(256, 2) gemm_mlp1(int wtoff, const float* __restrict__ bias,
                                                    const float* __restrict__ gamma,
                                                    const float* __restrict__ beta) {
    extern __shared__ char smem[];
    __half* SA = (__half*)smem;             // 64 x ALD
    __half* SB = SA + 64 * ALD;             // 256 x ALD
    float* SC = (float*)smem;               // 64 x CLD2 after mainloop (66560 B < 87040)

    const int tid = threadIdx.x;
    const int w = tid >> 5, lane = tid & 31;
    const int rg = w >> 2;   // 0..1: 32-row group
    const int cg = w & 3;    // 0..3: 64-col group
    const int m0 = blockIdx.x * 64;

    for (int idx = tid; idx < 64 * 16; idx += 256) {
        int row = idx >> 4, seg = idx & 15;
        uint4 v = make_uint4(0u, 0u, 0u, 0u);
        if (m0 + row < NN)
            v = *reinterpret_cast<const uint4*>(&d_noh[(size_t)(m0 + row) * DD + seg * 8]);
        *reinterpret_cast<uint4*>(&SA[row * ALD + seg * 8]) = v;
    }
    for (int idx = tid; idx < 256 * 16; idx += 256) {
        int row = idx >> 4, seg = idx & 15;
        size_t src = (size_t)wtoff + (size_t)row * DD + seg * 8;
        *reinterpret_cast<uint4*>(&SB[row * ALD + seg * 8]) =
            *reinterpret_cast<const uint4*>(&d_wtb[src]);
    }
    __syncthreads();

    wmma::fragment<wmma::accumulator, 16, 16, 16, float> acc[2][4];
#pragma unroll
    for (int i = 0; i < 2; i++)
#pragma unroll
        for (int j = 0; j < 4; j++) wmma::fill_fragment(acc[i][j], 0.0f);
#pragma unroll
    for (int ks = 0; ks < 8; ks++) {
        wmma::fragment<wmma::matrix_a, 16, 16, 16, __half, wmma::row_major> a[2];
#pragma unroll
        for (int i = 0; i < 2; i++)
            wmma::load_matrix_sync(a[i], &SA[(rg * 32 + i * 16) * ALD + ks * 16], ALD);
#pragma unroll
        for (int j = 0; j < 4; j++) {
            wmma::fragment<wmma::matrix_b, 16, 16, 16, __half, wmma::col_major> b;
            wmma::load_matrix_sync(b, &SB[(cg * 64 + j * 16) * ALD + ks * 16], ALD);
#pragma unroll
            for (int i = 0; i < 2; i++)
                wmma::mma_sync(acc[i][j], a[i], b, acc[i][j]);
        }
    }
    __syncthreads();
#pragma unroll
    for (int i = 0; i < 2; i++)
#pragma unroll
        for (int j = 0; j < 4; j++)
            wmma::store_matrix_sync(&SC[(rg * 32 + i * 16) * CLD2 + cg * 64 + j * 16],
                                    acc[i][j], CLD2, wmma::mem_row_major);
    __syncthreads();

    // LN(256)+relu epilogue: warp w owns rows w*8 .. w*8+7
    const int c1 = lane * 4, c2 = DD + lane * 4;
    float4 bA = *reinterpret_cast<const float4*>(&bias[c1]);
    float4 bB = *reinterpret_cast<const float4*>(&bias[c2]);
    float4 g1 = *reinterpret_cast<const float4*>(&gamma[c1]);
    float4 g2 = *reinterpret_cast<const float4*>(&gamma[c2]);
    float4 t1 = *reinterpret_cast<const float4*>(&beta[c1]);
    float4 t2 = *reinterpret_cast<const float4*>(&beta[c2]);
#pragma unroll 1
    for (int rr = 0; rr < 8; rr++) {
        int row = w * 8 + rr;
        int r = m0 + row;
        if (r >= NN) continue;
        float4 a = *reinterpret_cast<const float4*>(&SC[row * CLD2 + c1]);
        float4 b = *reinterpret_cast<const float4*>(&SC[row * CLD2 + c2]);
        a.x += bA.x; a.y += bA.y; a.z += bA.z; a.w += bA.w;
        b.x += bB.x; b.y += bB.y; b.z += bB.z; b.w += bB.w;
        float s = warp_sum(a.x + a.y + a.z + a.w + b.x + b.y + b.z + b.w);
        float mu = s * (1.0f / HH);
        float ax = a.x - mu, ay = a.y - mu, az = a.z - mu, aw = a.w - mu;
        float bx = b.x - mu, by = b.y - mu, bz = b.z - mu, bw = b.w - mu;
        float ss = warp_sum(ax * ax + ay * ay + az * az + aw * aw + bx * bx + by * by + bz * bz + bw * bw);
        float inv = rsqrtf(ss * (1.0f / HH) + 1e-5f);
        float4 o1, o2;
        o1.x = fmaxf(ax * inv * g1.x + t1.x, 0.f);
        o1.y = fmaxf(ay * inv * g1.y + t1.y, 0.f);
        o1.z = fmaxf(az * inv * g1.z + t1.z, 0.f);
        o1.w = fmaxf(aw * inv * g1.w + t1.w, 0.f);
        o2.x = fmaxf(bx * inv * g2.x + t2.x, 0.f);
        o2.y = fmaxf(by * inv * g2.y + t2.y, 0.f);
        o2.z = fmaxf(bz * inv * g2.z + t2.z, 0.f);
        o2.w = fmaxf(bw * inv * g2.w + t2.w, 0.f);
        *reinterpret_cast<uint2*>(&d_zh[(size_t)r * HH + c1]) = to_h4(o1);
        *reinterpret_cast<uint2*>(&d_zh[(size_t)r * HH + c2]) = to_h4(o2);
    }
}

// ---------------- launch ----------------
#define OFF_ENC 0
#define OFF_W1(i) (16384 + (i) * 32768)
#define OFF_W2(i) (16384 + 6 * 32768 + (i) * 32768)
#define OFF_LIN (16384 + 12 * 32768)

extern "C" void kernel_launch(void* const* d_in, const int* in_sizes, int n_in,
                              void* d_out, int out_size) {
    const float* x     = (const float*)d_in[0];
    const void*  ei    = d_in[1];
    const float* enc_W = (const float*)d_in[2];
    const float* enc_b = (const float*)d_in[3];
    const float* ln_g  = (const float*)d_in[4];
    const float* ln_b  = (const float*)d_in[5];
    const float* tt    = (const float*)d_in[6];
    const float* W1    = (const float*)d_in[7];
    const float* b1    = (const float*)d_in[8];
    const float* mg    = (const float*)d_in[9];
    const float* mb    = (const float*)d_in[10];
    const float* W2    = (const float*)d_in[11];
    const float* b2    = (const float*)d_in[12];
    const float* lW1   = (const float*)d_in[13];
    const float* lb1   = (const float*)d_in[14];
    const float* lW2   = (const float*)d_in[15];
    const float* lb2   = (const float*)d_in[16];
    float* out = (float*)d_out;

    const int SM_STD  = (64 + 128) * ALD * 2;   // 52224
    const int SM_MLP1 = (64 + 256) * ALD * 2;   // 87040 (>= SC 66560)
    cudaFuncSetAttribute(gemm_std<128, false, false, true,  false, false>, cudaFuncAttributeMaxDynamicSharedMemorySize, SM_STD);
    cudaFuncSetAttribute(gemm_std<256, true,  true,  true,  false, false>, cudaFuncAttributeMaxDynamicSharedMemorySize, SM_STD);
    cudaFuncSetAttribute(gemm_std<256, true,  true,  false, false, false>, cudaFuncAttributeMaxDynamicSharedMemorySize, SM_STD);
    cudaFuncSetAttribute(gemm_std<128, false, false, false, true,  true >, cudaFuncAttributeMaxDynamicSharedMemorySize, SM_STD);
    cudaFuncSetAttribute(gemm_mlp1, cudaFuncAttributeMaxDynamicSharedMemorySize, SM_MLP1);

    k_tsplit_all<<<(WT_TOTAL + 255) / 256, 256>>>(enc_W, W1, W2, lW1);

    k_probe<<<1, 256>>>(ei);
    k_zero_deg<<<(NN + 255) / 256, 256>>>();
    k_count<<<(EE + 255) / 256, 256>>>(ei);
    k_scan1<<<NSCB, SCB>>>();
    k_scan2<<<1, SCB>>>();
    k_scan3<<<NSCB, SCB>>>();
    k_fill<<<(EE + 255) / 256, 256>>>(ei);

    const int NWBLK = (NN * 32 + 255) / 256;
    const int MB64 = (NN + 63) / 64;     // 782

    // encoder: d_h = x @ enc_W + enc_b; fused LN+msg for layer 0
    gemm_std<128, false, false, true, false, false><<<MB64, 256, SM_STD>>>(
        x, 0, OFF_ENC, enc_b, ln_g, ln_b, tt, 0, nullptr, nullptr, nullptr);

    for (int i = 0; i < LL; i++) {
        k_agg<<<NWBLK, 256>>>();
        gemm_mlp1<<<MB64, 256, SM_MLP1>>>(OFF_W1(i), b1 + i * HH, mg + i * HH, mb + i * HH);
        if (i < LL - 1) {
            gemm_std<256, true, true, true, false, false><<<MB64, 256, SM_STD>>>(
                nullptr, 0, OFF_W2(i), b2 + i * DD,
                ln_g + (i + 1) * DD, ln_b + (i + 1) * DD, tt, i + 1, nullptr, nullptr, nullptr);
        } else {
            gemm_std<256, true, true, false, false, false><<<MB64, 256, SM_STD>>>(
                nullptr, 0, OFF_W2(i), b2 + i * DD, nullptr, nullptr, nullptr, 0,
                nullptr, nullptr, nullptr);
        }
    }

    // lin + fused head: A = d_h (Aid 1)
    gemm_std<128, false, false, false, true, true><<<MB64, 256, SM_STD>>>(
        nullptr, 1, OFF_LIN, lb1, nullptr, nullptr, nullptr, 0, lW2, lb2, out);
}

// round 16
// speedup vs baseline: 1.1380x; 1.1380x over previous
#include <cuda_runtime.h>
#include <cuda_fp16.h>
#include <mma.h>
#include <cstdint>

using namespace nvcuda;

#define NN 50000
#define EE 600000
#define DD 128
#define HH 256
#define LL 6
#define SCB 256
#define NSCB ((NN + SCB - 1) / SCB)   // 196

__device__ __align__(128) float d_h [NN * DD];
__device__ __align__(128) float d_g [NN * DD];
__device__ __align__(128) __half2 d_pqh[NN * DD];
__device__ __align__(16) __half d_noh[NN * DD];   // agg+g, fp16
__device__ __align__(16) __half d_zh [NN * HH];   // MLP hidden, fp16
__device__ int d_deg[NN];
__device__ int d_rowptr[NN + 1];
__device__ int d_cursor[NN];
__device__ int d_colsrc[EE];
__device__ int d_blksum[NSCB];
__device__ int d_is64;

#define WT_TOTAL 425984
__device__ __align__(16) __half d_wtb[WT_TOTAL];  // weights, single fp16

__device__ __forceinline__ int edge_at(const void* ei, int is64, size_t pos) {
    int v;
    if (is64) v = (int)((const long long*)ei)[pos];
    else      v = ((const int*)ei)[pos];
    if (v < 0) v = 0;
    if (v >= NN) v = NN - 1;
    return v;
}

__global__ void k_probe(const void* ei) {
    __shared__ int bad;
    if (threadIdx.x == 0) bad = 0;
    __syncthreads();
    const long long* p = (const long long*)ei;
    for (int i = threadIdx.x; i < 1024; i += blockDim.x) {
        long long v = p[i];
        if (v < 0 || v >= NN) bad = 1;
    }
    __syncthreads();
    if (threadIdx.x == 0) d_is64 = bad ? 0 : 1;
}

__global__ void k_zero_deg() {
    int i = blockIdx.x * blockDim.x + threadIdx.x;
    if (i < NN) d_deg[i] = 0;
}
__global__ void k_count(const void* __restrict__ ei) {
    int e = blockIdx.x * blockDim.x + threadIdx.x;
    if (e < EE) atomicAdd(&d_deg[edge_at(ei, d_is64, (size_t)EE + e)], 1);
}
__global__ void k_scan1() {
    __shared__ int sm[SCB];
    int t = threadIdx.x;
    int i = blockIdx.x * SCB + t;
    sm[t] = (i < NN) ? d_deg[i] : 0;
    __syncthreads();
#pragma unroll
    for (int off = SCB / 2; off; off >>= 1) {
        if (t < off) sm[t] += sm[t + off];
        __syncthreads();
    }
    if (t == 0) d_blksum[blockIdx.x] = sm[0];
}
__global__ void k_scan2() {
    __shared__ int sm[SCB];
    int t = threadIdx.x;
    int v = (t < NSCB) ? d_blksum[t] : 0;
    sm[t] = v;
    __syncthreads();
#pragma unroll
    for (int off = 1; off < SCB; off <<= 1) {
        int u = (t >= off) ? sm[t - off] : 0;
        __syncthreads();
        sm[t] += u;
        __syncthreads();
    }
    if (t < NSCB) d_blksum[t] = sm[t] - v;
    if (t == SCB - 1) d_rowptr[NN] = sm[SCB - 1];
}
__global__ void k_scan3() {
    __shared__ int sm[SCB];
    int t = threadIdx.x;
    int i = blockIdx.x * SCB + t;
    int v = (i < NN) ? d_deg[i] : 0;
    sm[t] = v;
    __syncthreads();
#pragma unroll
    for (int off = 1; off < SCB; off <<= 1) {
        int u = (t >= off) ? sm[t - off] : 0;
        __syncthreads();
        sm[t] += u;
        __syncthreads();
    }
    int excl = sm[t] - v + d_blksum[blockIdx.x];
    if (i < NN) { d_rowptr[i] = excl; d_cursor[i] = excl; }
}
__global__ void k_fill(const void* __restrict__ ei) {
    int e = blockIdx.x * blockDim.x + threadIdx.x;
    if (e < EE) {
        int dst = edge_at(ei, d_is64, (size_t)EE + e);
        int src = edge_at(ei, d_is64, (size_t)e);
        int pos = atomicAdd(&d_cursor[dst], 1);
        if (pos >= 0 && pos < EE) d_colsrc[pos] = src;
    }
}

__global__ void k_tsplit_all(const float* __restrict__ encW, const float* __restrict__ W1,
                             const float* __restrict__ W2, const float* __restrict__ lW1) {
    int idx = blockIdx.x * blockDim.x + threadIdx.x;
    if (idx >= WT_TOTAL) return;
    float v;
    if (idx < 16384) {
        int n = idx >> 7, k = idx & 127;
        v = encW[k * 128 + n];
    } else if (idx < 409600) {
        int r = (idx - 16384) >> 15;
        int wi = (idx - 16384) & 32767;
        if (r < 6) {
            int n = wi >> 7, k = wi & 127;
            v = W1[(size_t)r * 32768 + k * 256 + n];
        } else {
            int n = wi >> 8, k = wi & 255;
            v = W2[(size_t)(r - 6) * 32768 + k * 128 + n];
        }
    } else {
        int wi = idx - 409600;
        int n = wi >> 7, k = wi & 127;
        v = lW1[k * 128 + n];
    }
    d_wtb[idx] = __float2half_rn(v);
}

__device__ __forceinline__ float warp_sum(float v) {
#pragma unroll
    for (int off = 16; off; off >>= 1) v += __shfl_xor_sync(0xffffffffu, v, off);
    return v;
}

__device__ __forceinline__ uint2 to_h4(float4 v) {
    __half2 h01 = __floats2half2_rn(v.x, v.y);
    __half2 h23 = __floats2half2_rn(v.z, v.w);
    return make_uint2(*reinterpret_cast<uint32_t*>(&h01), *reinterpret_cast<uint32_t*>(&h23));
}

__device__ __forceinline__ void pq_acc(uint4 u, float4& den, float4& num) {
    float2 f0 = __half22float2(*reinterpret_cast<__half2*>(&u.x));
    float2 f1 = __half22float2(*reinterpret_cast<__half2*>(&u.y));
    float2 f2 = __half22float2(*reinterpret_cast<__half2*>(&u.z));
    float2 f3 = __half22float2(*reinterpret_cast<__half2*>(&u.w));
    den.x += f0.x; num.x += f0.y;
    den.y += f1.x; num.y += f1.y;
    den.z += f2.x; num.z += f2.y;
    den.w += f3.x; num.w += f3.y;
}

// ---------------- standalone CSR gather, fp16 output ----------------
__global__ void k_agg() {
    int n = (blockIdx.x * blockDim.x + threadIdx.x) >> 5;
    if (n >= NN) return;
    int lane = threadIdx.x & 31;
    int beg = d_rowptr[n], end = d_rowptr[n + 1];
    float4 den = make_float4(0.f, 0.f, 0.f, 0.f);
    float4 num = make_float4(0.f, 0.f, 0.f, 0.f);
    int e = beg;
    for (; e + 3 < end; e += 4) {
        int s0 = d_colsrc[e + 0], s1 = d_colsrc[e + 1];
        int s2 = d_colsrc[e + 2], s3 = d_colsrc[e + 3];
        uint4 u0 = *reinterpret_cast<const uint4*>(&d_pqh[(size_t)s0 * DD + lane * 4]);
        uint4 u1 = *reinterpret_cast<const uint4*>(&d_pqh[(size_t)s1 * DD + lane * 4]);
        uint4 u2 = *reinterpret_cast<const uint4*>(&d_pqh[(size_t)s2 * DD + lane * 4]);
        uint4 u3 = *reinterpret_cast<const uint4*>(&d_pqh[(size_t)s3 * DD + lane * 4]);
        pq_acc(u0, den, num);
        pq_acc(u1, den, num);
        pq_acc(u2, den, num);
        pq_acc(u3, den, num);
    }
    for (; e < end; e++) {
        int s = d_colsrc[e];
        uint4 u = *reinterpret_cast<const uint4*>(&d_pqh[(size_t)s * DD + lane * 4]);
        pq_acc(u, den, num);
    }
    float4 gv = *reinterpret_cast<const float4*>(&d_g[(size_t)n * DD + lane * 4]);
    float4 o;
    o.x = gv.x + num.x / (den.x + 1e-16f);
    o.y = gv.y + num.y / (den.y + 1e-16f);
    o.z = gv.z + num.z / (den.z + 1e-16f);
    o.w = gv.w + num.w / (den.w + 1e-16f);
    *reinterpret_cast<uint2*>(&d_noh[(size_t)n * DD + lane * 4]) = to_h4(o);
}

#define ALD 136
#define CLD 132
#define CLD2 260

// ---------------- gemm_std: 64-row tiles, 3 CTAs/SM, 32x32 warp tiles, single-term fp16 ----------------
template <int TK, bool PRESPLIT, bool RESID, bool DO_MSG, bool RELU, bool HEAD>
__global__ void __launch_bounds__(256, 3) gemm_std(const float* Ap, int Aid, int wtoff,
                                                   const float* __restrict__ bias,
                                                   const float* __restrict__ gamma,
                                                   const float* __restrict__ beta,
                                                   const float* __restrict__ tptr, int li,
                                                   const float* __restrict__ w2h,
                                                   const float* __restrict__ b2h,
                                                   float* __restrict__ outp) {
    extern __shared__ char smem[];
    __half* SA = (__half*)smem;             // 64 x ALD
    __half* SB = SA + 64 * ALD;             // 128 x ALD
    float* SC = (float*)smem;

    const int tid = threadIdx.x;
    const int w = tid >> 5, lane = tid & 31;
    const int rg = w >> 2;
    const int cg = w & 3;
    const int m0 = blockIdx.x * 64;

    const float* __restrict__ A = (Aid == 1) ? d_h : Ap;

    wmma::fragment<wmma::accumulator, 16, 16, 16, float> acc[2][2];
#pragma unroll
    for (int i = 0; i < 2; i++)
#pragma unroll
        for (int j = 0; j < 2; j++) wmma::fill_fragment(acc[i][j], 0.0f);

    constexpr int CHUNKS = TK / 128;
    for (int kc = 0; kc < CHUNKS; kc++) {
        __syncthreads();
        if (PRESPLIT) {
            for (int idx = tid; idx < 64 * 16; idx += 256) {
                int row = idx >> 4, seg = idx & 15;
                uint4 v = make_uint4(0u, 0u, 0u, 0u);
                if (m0 + row < NN)
                    v = *reinterpret_cast<const uint4*>(&d_zh[(size_t)(m0 + row) * TK + kc * 128 + seg * 8]);
                *reinterpret_cast<uint4*>(&SA[row * ALD + seg * 8]) = v;
            }
        } else {
            for (int idx = tid; idx < 64 * 32; idx += 256) {
                int row = idx >> 5, seg = idx & 31;
                float4 v = make_float4(0.f, 0.f, 0.f, 0.f);
                if (m0 + row < NN)
                    v = *reinterpret_cast<const float4*>(&A[(size_t)(m0 + row) * TK + kc * 128 + seg * 4]);
                *reinterpret_cast<uint2*>(&SA[row * ALD + seg * 4]) = to_h4(v);
            }
        }
        for (int idx = tid; idx < 128 * 16; idx += 256) {
            int row = idx >> 4, seg = idx & 15;
            size_t src = (size_t)wtoff + (size_t)row * TK + kc * 128 + seg * 8;
            *reinterpret_cast<uint4*>(&SB[row * ALD + seg * 8]) =
                *reinterpret_cast<const uint4*>(&d_wtb[src]);
        }
        __syncthreads();
#pragma unroll
        for (int ks = 0; ks < 8; ks++) {
            wmma::fragment<wmma::matrix_a, 16, 16, 16, __half, wmma::row_major> a[2];
#pragma unroll
            for (int i = 0; i < 2; i++)
                wmma::load_matrix_sync(a[i], &SA[(rg * 32 + i * 16) * ALD + ks * 16], ALD);
#pragma unroll
            for (int j = 0; j < 2; j++) {
                wmma::fragment<wmma::matrix_b, 16, 16, 16, __half, wmma::col_major> b;
                wmma::load_matrix_sync(b, &SB[(cg * 32 + j * 16) * ALD + ks * 16], ALD);
#pragma unroll
                for (int i = 0; i < 2; i++)
                    wmma::mma_sync(acc[i][j], a[i], b, acc[i][j]);
            }
        }
    }
    __syncthreads();
#pragma unroll
    for (int i = 0; i < 2; i++)
#pragma unroll
        for (int j = 0; j < 2; j++)
            wmma::store_matrix_sync(&SC[(rg * 32 + i * 16) * CLD + cg * 32 + j * 16],
                                    acc[i][j], CLD, wmma::mem_row_major);
    __syncthreads();

    const int col = lane * 4;
    float tval = 0.f;
    if (DO_MSG) tval = tptr[li];
    float4 bi = *reinterpret_cast<const float4*>(&bias[col]);
    float4 gm, bt;
    if (DO_MSG) {
        gm = *reinterpret_cast<const float4*>(&gamma[col]);
        bt = *reinterpret_cast<const float4*>(&beta[col]);
    }
    float hw00 = 0.f, hw01 = 0.f, hw10 = 0.f, hw11 = 0.f, hw20 = 0.f, hw21 = 0.f, hw30 = 0.f, hw31 = 0.f;
    if (HEAD) {
        hw00 = w2h[(col + 0) * 2 + 0]; hw01 = w2h[(col + 0) * 2 + 1];
        hw10 = w2h[(col + 1) * 2 + 0]; hw11 = w2h[(col + 1) * 2 + 1];
        hw20 = w2h[(col + 2) * 2 + 0]; hw21 = w2h[(col + 2) * 2 + 1];
        hw30 = w2h[(col + 3) * 2 + 0]; hw31 = w2h[(col + 3) * 2 + 1];
    }
#pragma unroll 1
    for (int rr = 0; rr < 8; rr++) {
        int row = w * 8 + rr;
        int r = m0 + row;
        if (r >= NN) continue;
        float4 v = *reinterpret_cast<const float4*>(&SC[row * CLD + col]);
        v.x += bi.x; v.y += bi.y; v.z += bi.z; v.w += bi.w;
        if (RESID) {
            float4 h4 = *reinterpret_cast<const float4*>(&d_h[(size_t)r * DD + col]);
            v.x += h4.x; v.y += h4.y; v.z += h4.z; v.w += h4.w;
        }
        if (RELU) {
            v.x = fmaxf(v.x, 0.f); v.y = fmaxf(v.y, 0.f);
            v.z = fmaxf(v.z, 0.f); v.w = fmaxf(v.w, 0.f);
        }
        if (HEAD) {
            float a0 = v.x * hw00 + v.y * hw10 + v.z * hw20 + v.w * hw30;
            float a1 = v.x * hw01 + v.y * hw11 + v.z * hw21 + v.w * hw31;
            a0 = warp_sum(a0);
            a1 = warp_sum(a1);
            if (lane == 0) {
                outp[r * 2 + 0] = a0 + b2h[0];
                outp[r * 2 + 1] = a1 + b2h[1];
            }
            continue;
        }
        *reinterpret_cast<float4*>(&d_h[(size_t)r * DD + col]) = v;
        if (DO_MSG) {
            float s = warp_sum(v.x + v.y + v.z + v.w);
            float mu = s * (1.0f / DD);
            float dx = v.x - mu, dy = v.y - mu, dz = v.z - mu, dw = v.w - mu;
            float ss = warp_sum(dx * dx + dy * dy + dz * dz + dw * dw);
            float inv = rsqrtf(ss * (1.0f / DD) + 1e-5f);
            float g0 = fmaxf(dx * inv * gm.x + bt.x, 0.0f);
            float g1 = fmaxf(dy * inv * gm.y + bt.y, 0.0f);
            float g2 = fmaxf(dz * inv * gm.z + bt.z, 0.0f);
            float g3 = fmaxf(dw * inv * gm.w + bt.w, 0.0f);
            *reinterpret_cast<float4*>(&d_g[(size_t)r * DD + col]) = make_float4(g0, g1, g2, g3);
            float m0f = g0 + 1e-7f, m1f = g1 + 1e-7f, m2f = g2 + 1e-7f, m3f = g3 + 1e-7f;
            float p0 = __expf(tval * m0f), p1 = __expf(tval * m1f);
            float p2 = __expf(tval * m2f), p3 = __expf(tval * m3f);
            __half2 pq0 = __floats2half2_rn(p0, m0f * p0);
            __half2 pq1 = __floats2half2_rn(p1, m1f * p1);
            __half2 pq2 = __floats2half2_rn(p2, m2f * p2);
            __half2 pq3 = __floats2half2_rn(p3, m3f * p3);
            uint4 u = make_uint4(*reinterpret_cast<uint32_t*>(&pq0), *reinterpret_cast<uint32_t*>(&pq1),
                                 *reinterpret_cast<uint32_t*>(&pq2), *reinterpret_cast<uint32_t*>(&pq3));
            *reinterpret_cast<uint4*>(&d_pqh[(size_t)r * DD + col]) = u;
        }
    }
}

// ---------------- gemm_mlp1: 128x256 tile, 512 threads, 32x64 warp tiles (round-14 form) ----------------
__global__ void __launch_bounds__(512, 1) gemm_mlp1(int wtoff, const float* __restrict__ bias,
                                                    const float* __restrict__ gamma,
                                                    const float* __restrict__ beta) {
    extern __shared__ char smem[];
    __half* SA = (__half*)smem;             // 128 x ALD
    __half* SB = SA + 128 * ALD;            // 256 x ALD
    float* SC = (float*)smem;               // 128 x CLD2 (133120 B dominates)

    const int tid = threadIdx.x;
    const int w = tid >> 5, lane = tid & 31;
    const int rg = w >> 2;
    const int cg = w & 3;
    const int m0 = blockIdx.x * 128;

    for (int idx = tid; idx < 128 * 16; idx += 512) {
        int row = idx >> 4, seg = idx & 15;
        uint4 v = make_uint4(0u, 0u, 0u, 0u);
        if (m0 + row < NN)
            v = *reinterpret_cast<const uint4*>(&d_noh[(size_t)(m0 + row) * DD + seg * 8]);
        *reinterpret_cast<uint4*>(&SA[row * ALD + seg * 8]) = v;
    }
    for (int idx = tid; idx < 256 * 16; idx += 512) {
        int row = idx >> 4, seg = idx & 15;
        size_t src = (size_t)wtoff + (size_t)row * DD + seg * 8;
        *reinterpret_cast<uint4*>(&SB[row * ALD + seg * 8]) =
            *reinterpret_cast<const uint4*>(&d_wtb[src]);
    }
    __syncthreads();

    wmma::fragment<wmma::accumulator, 16, 16, 16, float> acc[2][4];
#pragma unroll
    for (int i = 0; i < 2; i++)
#pragma unroll
        for (int j = 0; j < 4; j++) wmma::fill_fragment(acc[i][j], 0.0f);
#pragma unroll
    for (int ks = 0; ks < 8; ks++) {
        wmma::fragment<wmma::matrix_a, 16, 16, 16, __half, wmma::row_major> a[2];
#pragma unroll
        for (int i = 0; i < 2; i++)
            wmma::load_matrix_sync(a[i], &SA[(rg * 32 + i * 16) * ALD + ks * 16], ALD);
#pragma unroll
        for (int j = 0; j < 4; j++) {
            wmma::fragment<wmma::matrix_b, 16, 16, 16, __half, wmma::col_major> b;
            wmma::load_matrix_sync(b, &SB[(cg * 64 + j * 16) * ALD + ks * 16], ALD);
#pragma unroll
            for (int i = 0; i < 2; i++)
                wmma::mma_sync(acc[i][j], a[i], b, acc[i][j]);
        }
    }
    __syncthreads();
#pragma unroll
    for (int i = 0; i < 2; i++)
#pragma unroll
        for (int j = 0; j < 4; j++)
            wmma::store_matrix_sync(&SC[(rg * 32 + i * 16) * CLD2 + cg * 64 + j * 16],
                                    acc[i][j], CLD2, wmma::mem_row_major);
    __syncthreads();

    const int c1 = lane * 4, c2 = DD + lane * 4;
    float4 bA = *reinterpret_cast<const float4*>(&bias[c1]);
    float4 bB = *reinterpret_cast<const float4*>(&bias[c2]);
    float4 g1 = *reinterpret_cast<const float4*>(&gamma[c1]);
    float4 g2 = *reinterpret_cast<const float4*>(&gamma[c2]);
    float4 t1 = *reinterpret_cast<const float4*>(&beta[c1]);
    float4 t2 = *reinterpret_cast<const float4*>(&beta[c2]);
#pragma unroll 1
    for (int rr = 0; rr < 8; rr++) {
        int row = w * 8 + rr;
        int r = m0 + row;
        if (r >= NN) continue;
        float4 a = *reinterpret_cast<const float4*>(&SC[row * CLD2 + c1]);
        float4 b = *reinterpret_cast<const float4*>(&SC[row * CLD2 + c2]);
        a.x += bA.x; a.y += bA.y; a.z += bA.z; a.w += bA.w;
        b.x += bB.x; b.y += bB.y; b.z += bB.z; b.w += bB.w;
        float s = warp_sum(a.x + a.y + a.z + a.w + b.x + b.y + b.z + b.w);
        float mu = s * (1.0f / HH);
        float ax = a.x - mu, ay = a.y - mu, az = a.z - mu, aw = a.w - mu;
        float bx = b.x - mu, by = b.y - mu, bz = b.z - mu, bw = b.w - mu;
        float ss = warp_sum(ax * ax + ay * ay + az * az + aw * aw + bx * bx + by * by + bz * bz + bw * bw);
        float inv = rsqrtf(ss * (1.0f / HH) + 1e-5f);
        float4 o1, o2;
        o1.x = fmaxf(ax * inv * g1.x + t1.x, 0.f);
        o1.y = fmaxf(ay * inv * g1.y + t1.y, 0.f);
        o1.z = fmaxf(az * inv * g1.z + t1.z, 0.f);
        o1.w = fmaxf(aw * inv * g1.w + t1.w, 0.f);
        o2.x = fmaxf(bx * inv * g2.x + t2.x, 0.f);
        o2.y = fmaxf(by * inv * g2.y + t2.y, 0.f);
        o2.z = fmaxf(bz * inv * g2.z + t2.z, 0.f);
        o2.w = fmaxf(bw * inv * g2.w + t2.w, 0.f);
        *reinterpret_cast<uint2*>(&d_zh[(size_t)r * HH + c1]) = to_h4(o1);
        *reinterpret_cast<uint2*>(&d_zh[(size_t)r * HH + c2]) = to_h4(o2);
    }
}

// ---------------- launch ----------------
#define OFF_ENC 0
#define OFF_W1(i) (16384 + (i) * 32768)
#define OFF_W2(i) (16384 + 6 * 32768 + (i) * 32768)
#define OFF_LIN (16384 + 12 * 32768)

extern "C" void kernel_launch(void* const* d_in, const int* in_sizes, int n_in,
                              void* d_out, int out_size) {
    const float* x     = (const float*)d_in[0];
    const void*  ei    = d_in[1];
    const float* enc_W = (const float*)d_in[2];
    const float* enc_b = (const float*)d_in[3];
    const float* ln_g  = (const float*)d_in[4];
    const float* ln_b  = (const float*)d_in[5];
    const float* tt    = (const float*)d_in[6];
    const float* W1    = (const float*)d_in[7];
    const float* b1    = (const float*)d_in[8];
    const float* mg    = (const float*)d_in[9];
    const float* mb    = (const float*)d_in[10];
    const float* W2    = (const float*)d_in[11];
    const float* b2    = (const float*)d_in[12];
    const float* lW1   = (const float*)d_in[13];
    const float* lb1   = (const float*)d_in[14];
    const float* lW2   = (const float*)d_in[15];
    const float* lb2   = (const float*)d_in[16];
    float* out = (float*)d_out;

    const int SM_STD  = (64 + 128) * ALD * 2;   // 52224
    const int SM_MLP1 = 128 * CLD2 * 4;         // 133120
    cudaFuncSetAttribute(gemm_std<128, false, false, true,  false, false>, cudaFuncAttributeMaxDynamicSharedMemorySize, SM_STD);
    cudaFuncSetAttribute(gemm_std<256, true,  true,  true,  false, false>, cudaFuncAttributeMaxDynamicSharedMemorySize, SM_STD);
    cudaFuncSetAttribute(gemm_std<256, true,  true,  false, false, false>, cudaFuncAttributeMaxDynamicSharedMemorySize, SM_STD);
    cudaFuncSetAttribute(gemm_std<128, false, false, false, true,  true >, cudaFuncAttributeMaxDynamicSharedMemorySize, SM_STD);
    cudaFuncSetAttribute(gemm_mlp1, cudaFuncAttributeMaxDynamicSharedMemorySize, SM_MLP1);

    k_tsplit_all<<<(WT_TOTAL + 255) / 256, 256>>>(enc_W, W1, W2, lW1);

    k_probe<<<1, 256>>>(ei);
    k_zero_deg<<<(NN + 255) / 256, 256>>>();
    k_count<<<(EE + 255) / 256, 256>>>(ei);
    k_scan1<<<NSCB, SCB>>>();
    k_scan2<<<1, SCB>>>();
    k_scan3<<<NSCB, SCB>>>();
    k_fill<<<(EE + 255) / 256, 256>>>(ei);

    const int NWBLK = (NN * 32 + 255) / 256;
    const int MB64 = (NN + 63) / 64;     // 782
    const int MB128 = (NN + 127) / 128;  // 391

    // encoder: d_h = x @ enc_W + enc_b; fused LN+msg for layer 0
    gemm_std<128, false, false, true, false, false><<<MB64, 256, SM_STD>>>(
        x, 0, OFF_ENC, enc_b, ln_g, ln_b, tt, 0, nullptr, nullptr, nullptr);

    for (int i = 0; i < LL; i++) {
        k_agg<<<NWBLK, 256>>>();
        gemm_mlp1<<<MB128, 512, SM_MLP1>>>(OFF_W1(i), b1 + i * HH, mg + i * HH, mb + i * HH);
        if (i < LL - 1) {
            gemm_std<256, true, true, true, false, false><<<MB64, 256, SM_STD>>>(
                nullptr, 0, OFF_W2(i), b2 + i * DD,
                ln_g + (i + 1) * DD, ln_b + (i + 1) * DD, tt, i + 1, nullptr, nullptr, nullptr);
        } else {
            gemm_std<256, true, true, false, false, false><<<MB64, 256, SM_STD>>>(
                nullptr, 0, OFF_W2(i), b2 + i * DD, nullptr, nullptr, nullptr, 0,
                nullptr, nullptr, nullptr);
        }
    }

    // lin + fused head: A = d_h (Aid 1)
    gemm_std<128, false, false, false, true, true><<<MB64, 256, SM_STD>>>(
        nullptr, 1, OFF_LIN, lb1, nullptr, nullptr, nullptr, 0, lW2, lb2, out);
}